// round 11
// baseline (speedup 1.0000x reference)
#include <cuda_runtime.h>
#include <cuda_fp16.h>
#include <cstdint>

// Problem constants
#define B_SZ   32768
#define N_VARS 64
#define H_SZ   64
#define TILE_M 128          // batch rows per CTA
#define G_NODES 8           // nodes per CTA (one per warp)
#define NODE_GROUPS 8       // 64 / 8
#define BTILES (B_SZ / TILE_M)   // 256
#define MTILES (TILE_M / 16)     // 8

// X tile in smem: fp16, padded row stride 72 halves (144B) -> conflict-free ldmatrix
#define XS_STRIDE 72

// smem layout (bytes)
#define SM_X    0
#define SM_X_SZ (TILE_M * XS_STRIDE * 2)                 // 18432
#define SM_W2   (SM_X + SM_X_SZ)                         // 18432
#define SM_W2_SZ (G_NODES * H_SZ * 4)                    // 2048
#define SM_WS   (SM_W2 + SM_W2_SZ)                       // 20480: B frags kt=2,3
#define SM_WS_SZ (G_NODES * 2 * 8 * 32 * 8)              // 32768
#define SM_OUT  (SM_WS + SM_WS_SZ)                       // 53248: [node][row][lq]
#define SM_OUT_SZ (G_NODES * TILE_M * 4 * 4)             // 16384
#define SM_TOTAL (SM_OUT + SM_OUT_SZ)                    // 69632  (x3 CTAs = 209KB)

// Pre-swizzled fp16 B fragments: [node][ktile(4)][ntile(8)][lane(32)] x uint2
__device__ uint2 g_wfrag[(size_t)N_VARS * 4 * 8 * 32];

__device__ __forceinline__ uint32_t h2_as_u32(__half2 h) {
    union { __half2 h; uint32_t u; } cvt;
    cvt.h = h;
    return cvt.u;
}

__device__ __forceinline__ uint32_t smem_u32(const void* p) {
    uint32_t a;
    asm("{ .reg .u64 t; cvta.to.shared.u64 t, %1; cvt.u32.u64 %0, t; }" : "=r"(a) : "l"(p));
    return a;
}

__device__ __forceinline__ void ldmatrix_x4(uint32_t r[4], uint32_t addr) {
    asm volatile("ldmatrix.sync.aligned.m8n8.x4.shared.b16 {%0,%1,%2,%3}, [%4];"
                 : "=r"(r[0]), "=r"(r[1]), "=r"(r[2]), "=r"(r[3]) : "r"(addr));
}

__device__ __forceinline__ void mma16816(float c[4], const uint32_t a[4],
                                         uint32_t b0, uint32_t b1) {
    asm volatile(
        "mma.sync.aligned.m16n8k16.row.col.f32.f16.f16.f32 "
        "{%0,%1,%2,%3}, {%4,%5,%6,%7}, {%8,%9}, {%0,%1,%2,%3};"
        : "+f"(c[0]), "+f"(c[1]), "+f"(c[2]), "+f"(c[3])
        : "r"(a[0]), "r"(a[1]), "r"(a[2]), "r"(a[3]), "r"(b0), "r"(b1));
}

__device__ __forceinline__ void lds_u2(uint2& v, uint32_t addr) {
    asm volatile("ld.shared.v2.u32 {%0,%1}, [%2];" : "=r"(v.x), "=r"(v.y) : "r"(addr));
}

// ---------------- prolog: build masked fp16 B fragments ----------------
__global__ void __launch_bounds__(256) wfrag_kernel(const float* __restrict__ W1,
                                                    const float* __restrict__ adj) {
    int idx = blockIdx.x * 256 + threadIdx.x;        // 65536 total
    int lane  = idx & 31;
    int ntile = (idx >> 5) & 7;
    int ktile = (idx >> 8) & 3;
    int node  = idx >> 10;
    int h  = ntile * 8 + (lane >> 2);
    int k0 = ktile * 16 + (lane & 3) * 2;

    const float* wrow = W1 + ((size_t)node * H_SZ + h) * N_VARS;
    float2 wlo = *(const float2*)(wrow + k0);
    float2 whi = *(const float2*)(wrow + k0 + 8);
    const float* arow = adj + node * N_VARS;
    float2 alo = *(const float2*)(arow + k0);
    float2 ahi = *(const float2*)(arow + k0 + 8);
    if (node == N_VARS - 1) {   // hidden_flag: last node keeps only feature 63
        alo.x = 0.f; alo.y = 0.f;
        ahi.x = 0.f;
        if (k0 + 9 != N_VARS - 1) ahi.y = 0.f;
    }
    uint2 r;
    r.x = h2_as_u32(__floats2half2_rn(wlo.x * alo.x, wlo.y * alo.y));
    r.y = h2_as_u32(__floats2half2_rn(whi.x * ahi.x, whi.y * ahi.y));
    g_wfrag[idx] = r;
}

// ---------------- main kernel ----------------
// One warp == one node. B kt{0,1} in 32 regs; kt{2,3} streamed from smem.
// 3 CTAs/SM target. Input convert fused. Quad partials via STS + final pass.
__global__ void __launch_bounds__(256, 3)
main_kernel(const float4* __restrict__ in4, const float* __restrict__ W2,
            float* __restrict__ out) {
    extern __shared__ char smem[];
    const int tid = threadIdx.x;
    const int lane = tid & 31, warp = tid >> 5;   // warp = node-in-group
    const int group = blockIdx.y;
    const int row0 = blockIdx.x * TILE_M;

    __half2* xs = (__half2*)(smem + SM_X);
    float* w2s = (float*)(smem + SM_W2);
    float* outs = (float*)(smem + SM_OUT);        // [node][row][lq] words

    // --- register B: kt 0,1 of this warp's node (32 regs) ---
    uint2 bf[2][8];
    {
        const uint2* src = g_wfrag + (size_t)(group * G_NODES + warp) * 1024 + lane;
#pragma unroll
        for (int kt = 0; kt < 2; kt++)
#pragma unroll
            for (int nt = 0; nt < 8; nt++)
                bf[kt][nt] = src[(kt * 8 + nt) * 32];
    }

    // --- smem B: kt 2,3 for all 8 nodes (32 KB) ---
    {
        uint4* dst = (uint4*)(smem + SM_WS);
#pragma unroll
        for (int it = 0; it < 8; it++) {
            int idx = tid + it * 256;             // 0..2047 uint4
            int node = idx >> 8, rem = idx & 255; // 256 uint4 per node
            dst[idx] = ((const uint4*)(g_wfrag
                        + ((size_t)(group * G_NODES + node) * 1024 + 512)))[rem];
        }
    }

    // --- W2 for this group (512 floats) ---
    if (tid < 128)
        ((float4*)w2s)[tid] = ((const float4*)(W2 + group * G_NODES * H_SZ))[tid];

    // --- load X tile from gmem fp32, apply straight-through gate, convert fp16 ---
#pragma unroll
    for (int it = 0; it < 8; it++) {
        int idx = tid + it * 256;             // 0..2047
        int r = idx >> 4, j = idx & 15;
        float4 v = in4[(size_t)(row0 + r) * 16 + j];
        if (j < 4) {
            v.x = v.x > 0.f ? 1.f : 0.f;
            v.y = v.y > 0.f ? 1.f : 0.f;
            v.z = v.z > 0.f ? 1.f : 0.f;
            v.w = v.w > 0.f ? 1.f : 0.f;
        }
        xs[r * (XS_STRIDE / 2) + j * 2]     = __floats2half2_rn(v.x, v.y);
        xs[r * (XS_STRIDE / 2) + j * 2 + 1] = __floats2half2_rn(v.z, v.w);
    }
    __syncthreads();

    const uint32_t sb = smem_u32(smem);
    const uint32_t xsb = sb + SM_X;
    const uint32_t wsb = sb + SM_WS + (uint32_t)(warp * 4096 + lane * 8);
    const int mtx = lane >> 3, rowm = lane & 7;
    const int lq = lane & 3;       // quad col id
    const int lr = lane >> 2;      // row-in-8
    const uint32_t arow_off = (uint32_t)(((mtx & 1) * 8 + rowm) * (XS_STRIDE * 2)
                                         + ((mtx >> 1) * 8) * 2);

    // --- W2 in registers: per-lane pair for each ntile ---
    float2 w2r[8];
#pragma unroll
    for (int nt = 0; nt < 8; nt++)
        w2r[nt] = *(const float2*)&w2s[warp * H_SZ + nt * 8 + lq * 2];

#pragma unroll 1
    for (int mt = 0; mt < MTILES; mt++) {
        const uint32_t mbase = xsb + (uint32_t)(mt * 16 * (XS_STRIDE * 2)) + arow_off;

        uint32_t a[4][4];
#pragma unroll
        for (int kt = 0; kt < 4; kt++)
            ldmatrix_x4(a[kt], mbase + (uint32_t)(kt * 32));

        float s0 = 0.f, s1 = 0.f;
#pragma unroll
        for (int nt = 0; nt < 8; nt++) {
            uint2 b2, b3;
            lds_u2(b2, wsb + (uint32_t)(nt * 256));          // kt=2
            lds_u2(b3, wsb + (uint32_t)(2048 + nt * 256));   // kt=3
            float c[4] = {0.f, 0.f, 0.f, 0.f};
            mma16816(c, a[0], bf[0][nt].x, bf[0][nt].y);
            mma16816(c, a[1], bf[1][nt].x, bf[1][nt].y);
            mma16816(c, a[2], b2.x, b2.y);
            mma16816(c, a[3], b3.x, b3.y);
            s0 = fmaf(fmaxf(c[0], 0.f), w2r[nt].x, s0);
            s0 = fmaf(fmaxf(c[1], 0.f), w2r[nt].y, s0);
            s1 = fmaf(fmaxf(c[2], 0.f), w2r[nt].x, s1);
            s1 = fmaf(fmaxf(c[3], 0.f), w2r[nt].y, s1);
        }
        outs[warp * (TILE_M * 4) + (mt * 16 + lr) * 4 + lq] = s0;
        outs[warp * (TILE_M * 4) + (mt * 16 + lr + 8) * 4 + lq] = s1;
    }
    __syncthreads();

    // --- final quad-reduce + coalesced store ---
    // thread -> (row = tid/2, node-quad = tid%2): 4 nodes, one float4 store
    {
        int r = tid >> 1, h4 = tid & 1;
        float o[4];
#pragma unroll
        for (int i = 0; i < 4; i++) {
            int n = h4 * 4 + i;
            float4 p = *(const float4*)&outs[n * (TILE_M * 4) + r * 4];
            o[i] = (p.x + p.y) + (p.z + p.w);
        }
        *(float4*)(out + (size_t)(row0 + r) * N_VARS + group * G_NODES + h4 * 4)
            = make_float4(o[0], o[1], o[2], o[3]);
    }
}

// ---------------- launch ----------------
extern "C" void kernel_launch(void* const* d_in, const int* in_sizes, int n_in,
                              void* d_out, int out_size) {
    // metadata order: t, inputs, W1, W2, adjacency, discrete_mask
    const float* inputs = (const float*)d_in[1];
    const float* W1     = (const float*)d_in[2];
    const float* W2     = (const float*)d_in[3];
    const float* adj    = (const float*)d_in[4];
    float* out = (float*)d_out;

    static bool attr_set = false;
    if (!attr_set) {
        cudaFuncSetAttribute(main_kernel, cudaFuncAttributeMaxDynamicSharedMemorySize,
                             SM_TOTAL);
        attr_set = true;
    }

    wfrag_kernel<<<256, 256>>>(W1, adj);
    main_kernel<<<dim3(BTILES, NODE_GROUPS), 256, SM_TOTAL>>>(
        (const float4*)inputs, W2, out);
}

// round 13
// speedup vs baseline: 1.1577x; 1.1577x over previous
#include <cuda_runtime.h>
#include <cuda_fp16.h>
#include <cstdint>

// Problem constants
#define B_SZ   32768
#define N_VARS 64
#define H_SZ   64
#define N_DISC 16
#define TILE_M 128          // batch rows per X tile
#define G_NODES 8           // nodes per CTA (one per warp)
#define NODE_GROUPS 8
#define BTILES (B_SZ / TILE_M)   // 256
#define MTILES (TILE_M / 16)     // 8
#define NSLICES 37               // 37*8 = 296 CTAs = 2 per SM (148 SMs)

// X tile in smem: fp16, padded row stride 72 halves (144B) -> conflict-free ldmatrix
#define XS_STRIDE 72
#define XROW_B (XS_STRIDE * 2)   // 144

// smem layout (bytes)
#define SM_X0   0
#define SM_X1   (TILE_M * XROW_B)                        // 18432
#define SM_W2   (2 * TILE_M * XROW_B)                    // 36864
#define SM_W2_SZ (G_NODES * H_SZ * 4)                    // 2048
#define SM_OUT  (SM_W2 + SM_W2_SZ)                       // 38912
#define SM_OUT_SZ (TILE_M * G_NODES * 4)                 // 4096
#define SM_TOTAL (SM_OUT + SM_OUT_SZ)                    // 43008 (x2 CTAs = 86KB)

__device__ __half g_x16[(size_t)B_SZ * N_VARS];          // 4 MB fp16 gated inputs
// Pre-swizzled fp16 B fragments: [node][ktile(4)][ntile(8)][lane(32)] x uint2
__device__ uint2 g_wfrag[(size_t)N_VARS * 4 * 8 * 32];

__device__ __forceinline__ uint32_t h2_as_u32(__half2 h) {
    union { __half2 h; uint32_t u; } cvt;
    cvt.h = h;
    return cvt.u;
}
__device__ __forceinline__ uint32_t smem_u32(const void* p) {
    uint32_t a;
    asm("{ .reg .u64 t; cvta.to.shared.u64 t, %1; cvt.u32.u64 %0, t; }" : "=r"(a) : "l"(p));
    return a;
}
__device__ __forceinline__ void ldmatrix_x4(uint32_t r[4], uint32_t addr) {
    asm volatile("ldmatrix.sync.aligned.m8n8.x4.shared.b16 {%0,%1,%2,%3}, [%4];"
                 : "=r"(r[0]), "=r"(r[1]), "=r"(r[2]), "=r"(r[3]) : "r"(addr));
}
__device__ __forceinline__ void mma16816(float c[4], const uint32_t a[4],
                                         uint32_t b0, uint32_t b1) {
    asm volatile(
        "mma.sync.aligned.m16n8k16.row.col.f32.f16.f16.f32 "
        "{%0,%1,%2,%3}, {%4,%5,%6,%7}, {%8,%9}, {%0,%1,%2,%3};"
        : "+f"(c[0]), "+f"(c[1]), "+f"(c[2]), "+f"(c[3])
        : "r"(a[0]), "r"(a[1]), "r"(a[2]), "r"(a[3]), "r"(b0), "r"(b1));
}
__device__ __forceinline__ void cp_async16(uint32_t dst, const void* src) {
    asm volatile("cp.async.cg.shared.global [%0], [%1], 16;" :: "r"(dst), "l"(src));
}
#define CP_COMMIT() asm volatile("cp.async.commit_group;" ::: "memory")
#define CP_WAIT1()  asm volatile("cp.async.wait_group 1;" ::: "memory")

// ---------------- kernel 1: input convert (straight-through gate) ----------------
// Discrete vars are indices < N_DISC (hardcoded; matches reference input_type_list).
__global__ void cvt_kernel(const float4* __restrict__ in) {
    int i = blockIdx.x * blockDim.x + threadIdx.x;   // over B*N/4
    float4 v = in[i];
    int nb = (i * 4) & (N_VARS - 1);
    if (nb < N_DISC) {   // whole float4 inside the discrete range (16 % 4 == 0)
        v.x = v.x > 0.f ? 1.f : 0.f;
        v.y = v.y > 0.f ? 1.f : 0.f;
        v.z = v.z > 0.f ? 1.f : 0.f;
        v.w = v.w > 0.f ? 1.f : 0.f;
    }
    __half2* dst = (__half2*)g_x16;
    dst[i * 2 + 0] = __floats2half2_rn(v.x, v.y);
    dst[i * 2 + 1] = __floats2half2_rn(v.z, v.w);
}

// ---------------- prolog: build masked fp16 B fragments ----------------
__global__ void __launch_bounds__(256) wfrag_kernel(const float* __restrict__ W1,
                                                    const float* __restrict__ adj) {
    int idx = blockIdx.x * 256 + threadIdx.x;        // 65536 total
    int lane  = idx & 31;
    int ntile = (idx >> 5) & 7;
    int ktile = (idx >> 8) & 3;
    int node  = idx >> 10;
    int h  = ntile * 8 + (lane >> 2);
    int k0 = ktile * 16 + (lane & 3) * 2;

    const float* wrow = W1 + ((size_t)node * H_SZ + h) * N_VARS;
    float2 wlo = *(const float2*)(wrow + k0);
    float2 whi = *(const float2*)(wrow + k0 + 8);
    const float* arow = adj + node * N_VARS;
    float2 alo = *(const float2*)(arow + k0);
    float2 ahi = *(const float2*)(arow + k0 + 8);
    if (node == N_VARS - 1) {   // hidden_flag: last node keeps only feature 63
        alo.x = 0.f; alo.y = 0.f;
        ahi.x = 0.f;
        if (k0 + 9 != N_VARS - 1) ahi.y = 0.f;
    }
    uint2 r;
    r.x = h2_as_u32(__floats2half2_rn(wlo.x * alo.x, wlo.y * alo.y));
    r.y = h2_as_u32(__floats2half2_rn(whi.x * ahi.x, whi.y * ahi.y));
    g_wfrag[idx] = r;
}

// ---------------- main kernel: persistent CTAs, double-buffered X ----------------
__global__ void __launch_bounds__(256, 2)
main_kernel(const float* __restrict__ W2, float* __restrict__ out) {
    extern __shared__ char smem[];
    const int tid = threadIdx.x;
    const int lane = tid & 31, warp = tid >> 5;   // warp = node-in-group
    const int slice = blockIdx.x;                 // 0..36
    const int group = blockIdx.y;                 // 0..7

    float* w2s = (float*)(smem + SM_W2);
    float* outs = (float*)(smem + SM_OUT);
    const uint32_t sb = smem_u32(smem);

    // --- B fragments for this warp's node: 64 regs (ONCE per CTA) ---
    uint2 bf[4][8];
    {
        const uint2* src = g_wfrag + (size_t)(group * G_NODES + warp) * 1024 + lane;
#pragma unroll
        for (int kt = 0; kt < 4; kt++)
#pragma unroll
            for (int nt = 0; nt < 8; nt++)
                bf[kt][nt] = src[(kt * 8 + nt) * 32];
    }
    // --- W2 for this group ---
    if (tid < 128)
        ((float4*)w2s)[tid] = ((const float4*)(W2 + group * G_NODES * H_SZ))[tid];
    __syncthreads();

    const int mtx = lane >> 3, rowm = lane & 7;
    const int lq = lane & 3;       // quad col id
    const int lr = lane >> 2;      // row-in-8
    const uint32_t arow_off = (uint32_t)(((mtx & 1) * 8 + rowm) * XROW_B
                                         + ((mtx >> 1) * 8) * 2);
    float2 w2r[8];
#pragma unroll
    for (int nt = 0; nt < 8; nt++)
        w2r[nt] = *(const float2*)&w2s[warp * H_SZ + nt * 8 + lq * 2];

    // prefetch helper indexing: per-thread 4 chunks of 16B
    const int pr = tid >> 3, pseg = tid & 7;    // rows tid/8 + 32*it

    // --- prefetch first tile into buf0 ---
    {
        const char* src = (const char*)(g_x16 + (size_t)slice * TILE_M * N_VARS);
#pragma unroll
        for (int it = 0; it < 4; it++) {
            int r = pr + it * 32;
            cp_async16(sb + SM_X0 + (uint32_t)(r * XROW_B + pseg * 16),
                       src + r * 128 + pseg * 16);
        }
    }
    CP_COMMIT();

    int parity = 0;
#pragma unroll 1
    for (int bt = slice; bt < BTILES; bt += NSLICES) {
        // prefetch next tile into the other buffer (safe: all warps passed the
        // trailing __syncthreads of the previous iteration, so reads are done)
        {
            int nxt = bt + NSLICES;
            if (nxt < BTILES) {
                const char* src = (const char*)(g_x16 + (size_t)nxt * TILE_M * N_VARS);
                uint32_t dstb = sb + (parity ? SM_X0 : SM_X1);
#pragma unroll
                for (int it = 0; it < 4; it++) {
                    int r = pr + it * 32;
                    cp_async16(dstb + (uint32_t)(r * XROW_B + pseg * 16),
                               src + r * 128 + pseg * 16);
                }
            }
        }
        CP_COMMIT();
        CP_WAIT1();            // current tile's loads complete
        __syncthreads();       // visible to all warps; outs free for rewrite

        const uint32_t xsb = sb + (parity ? SM_X1 : SM_X0);
#pragma unroll 1
        for (int mt = 0; mt < MTILES; mt++) {
            const uint32_t mbase = xsb + (uint32_t)(mt * 16 * XROW_B) + arow_off;
            uint32_t a[4][4];
#pragma unroll
            for (int kt = 0; kt < 4; kt++)
                ldmatrix_x4(a[kt], mbase + (uint32_t)(kt * 32));

            float s0 = 0.f, s1 = 0.f;
#pragma unroll
            for (int nt = 0; nt < 8; nt++) {
                float c[4] = {0.f, 0.f, 0.f, 0.f};
#pragma unroll
                for (int kt = 0; kt < 4; kt++)
                    mma16816(c, a[kt], bf[kt][nt].x, bf[kt][nt].y);
                s0 = fmaf(fmaxf(c[0], 0.f), w2r[nt].x, s0);
                s0 = fmaf(fmaxf(c[1], 0.f), w2r[nt].y, s0);
                s1 = fmaf(fmaxf(c[2], 0.f), w2r[nt].x, s1);
                s1 = fmaf(fmaxf(c[3], 0.f), w2r[nt].y, s1);
            }
            s0 += __shfl_xor_sync(0xFFFFFFFF, s0, 1);
            s0 += __shfl_xor_sync(0xFFFFFFFF, s0, 2);
            s1 += __shfl_xor_sync(0xFFFFFFFF, s1, 1);
            s1 += __shfl_xor_sync(0xFFFFFFFF, s1, 2);
            if (lq == 0) {
                outs[(mt * 16 + lr) * G_NODES + warp] = s0;
                outs[(mt * 16 + lr + 8) * G_NODES + warp] = s1;
            }
        }
        __syncthreads();       // outs complete; X buffer free for future prefetch

        // coalesced store: 128 rows x 8 floats = 256 float4
        {
            int r = tid >> 1, q = tid & 1;
            float4 v = ((const float4*)outs)[tid];
            *(float4*)(out + (size_t)(bt * TILE_M + r) * N_VARS
                       + group * G_NODES + q * 4) = v;
        }
        parity ^= 1;
    }
}

// ---------------- launch ----------------
extern "C" void kernel_launch(void* const* d_in, const int* in_sizes, int n_in,
                              void* d_out, int out_size) {
    // metadata order: t, inputs, W1, W2, adjacency, discrete_mask
    const float* inputs = (const float*)d_in[1];
    const float* W1     = (const float*)d_in[2];
    const float* W2     = (const float*)d_in[3];
    const float* adj    = (const float*)d_in[4];
    float* out = (float*)d_out;

    static bool attr_set = false;
    if (!attr_set) {
        cudaFuncSetAttribute(main_kernel, cudaFuncAttributeMaxDynamicSharedMemorySize,
                             SM_TOTAL);
        attr_set = true;
    }

    cvt_kernel<<<(B_SZ * N_VARS / 4) / 256, 256>>>((const float4*)inputs);
    wfrag_kernel<<<256, 256>>>(W1, adj);
    main_kernel<<<dim3(NSLICES, NODE_GROUPS), 256, SM_TOTAL>>>(W2, out);
}

// round 14
// speedup vs baseline: 1.1766x; 1.0163x over previous
#include <cuda_runtime.h>
#include <cuda_fp16.h>
#include <cstdint>

// Problem constants
#define B_SZ   32768
#define N_VARS 64
#define H_SZ   64
#define N_DISC 16
#define TILE_M 128          // batch rows per X tile
#define G_NODES 8           // nodes per CTA (one per warp)
#define NODE_GROUPS 8
#define BTILES (B_SZ / TILE_M)   // 256
#define MTILES (TILE_M / 16)     // 8
#define NSLICES 37               // 37*8 = 296 CTAs = 2 per SM (148 SMs)

// X tile in smem: fp16, padded row stride 72 halves (144B) -> conflict-free ldmatrix
#define XS_STRIDE 72
#define XROW_B (XS_STRIDE * 2)   // 144

// smem layout (bytes)
#define SM_X0   0
#define SM_X1   (TILE_M * XROW_B)                        // 18432
#define SM_W2   (2 * TILE_M * XROW_B)                    // 36864
#define SM_W2_SZ (G_NODES * H_SZ * 4)                    // 2048
#define SM_OUT  (SM_W2 + SM_W2_SZ)                       // 38912
#define SM_OUT_SZ (TILE_M * G_NODES * 4)                 // 4096
#define SM_TOTAL (SM_OUT + SM_OUT_SZ)                    // 43008 (x2 CTAs = 86KB)

// prep kernel partition
#define CVT_BLOCKS  1024    // 1024*256 threads * 8 floats = 2M elements
#define FRAG_BLOCKS 256

__device__ __half g_x16[(size_t)B_SZ * N_VARS];          // 4 MB fp16 gated inputs
// Pre-swizzled fp16 B fragments: [node][ktile(4)][ntile(8)][lane(32)] x uint2
__device__ uint2 g_wfrag[(size_t)N_VARS * 4 * 8 * 32];

__device__ __forceinline__ uint32_t h2_as_u32(__half2 h) {
    union { __half2 h; uint32_t u; } cvt;
    cvt.h = h;
    return cvt.u;
}
__device__ __forceinline__ uint32_t smem_u32(const void* p) {
    uint32_t a;
    asm("{ .reg .u64 t; cvta.to.shared.u64 t, %1; cvt.u32.u64 %0, t; }" : "=r"(a) : "l"(p));
    return a;
}
__device__ __forceinline__ void ldmatrix_x4(uint32_t r[4], uint32_t addr) {
    asm volatile("ldmatrix.sync.aligned.m8n8.x4.shared.b16 {%0,%1,%2,%3}, [%4];"
                 : "=r"(r[0]), "=r"(r[1]), "=r"(r[2]), "=r"(r[3]) : "r"(addr));
}
__device__ __forceinline__ void mma16816(float c[4], const uint32_t a[4],
                                         uint32_t b0, uint32_t b1) {
    asm volatile(
        "mma.sync.aligned.m16n8k16.row.col.f32.f16.f16.f32 "
        "{%0,%1,%2,%3}, {%4,%5,%6,%7}, {%8,%9}, {%0,%1,%2,%3};"
        : "+f"(c[0]), "+f"(c[1]), "+f"(c[2]), "+f"(c[3])
        : "r"(a[0]), "r"(a[1]), "r"(a[2]), "r"(a[3]), "r"(b0), "r"(b1));
}
__device__ __forceinline__ void cp_async16(uint32_t dst, const void* src) {
    asm volatile("cp.async.cg.shared.global [%0], [%1], 16;" :: "r"(dst), "l"(src));
}
#define CP_COMMIT() asm volatile("cp.async.commit_group;" ::: "memory")
#define CP_WAIT1()  asm volatile("cp.async.wait_group 1;" ::: "memory")

__device__ __forceinline__ uint32_t gate2(float x, float y, bool disc) {
    if (disc) {
        x = x > 0.f ? 1.f : 0.f;
        y = y > 0.f ? 1.f : 0.f;
    }
    return h2_as_u32(__floats2half2_rn(x, y));
}

// ---------------- prep: fused input convert + masked B fragments ----------------
__global__ void __launch_bounds__(256) prep_kernel(const float4* __restrict__ in,
                                                   const float* __restrict__ W1,
                                                   const float* __restrict__ adj) {
    if (blockIdx.x < CVT_BLOCKS) {
        // ---- convert: 2 float4 -> one uint4 (4 half2) per thread ----
        int i = blockIdx.x * 256 + threadIdx.x;      // 0..262143, 8 floats each
        float4 v0 = in[i * 2 + 0];
        float4 v1 = in[i * 2 + 1];
        bool disc = ((i * 8) & (N_VARS - 1)) < N_DISC;   // 8-aligned, 16-divisible
        uint4 o;
        o.x = gate2(v0.x, v0.y, disc);
        o.y = gate2(v0.z, v0.w, disc);
        o.z = gate2(v1.x, v1.y, disc);
        o.w = gate2(v1.z, v1.w, disc);
        ((uint4*)g_x16)[i] = o;
    } else {
        // ---- build masked fp16 B fragments ----
        int idx = (blockIdx.x - CVT_BLOCKS) * 256 + threadIdx.x;  // 65536 total
        int lane  = idx & 31;
        int ntile = (idx >> 5) & 7;
        int ktile = (idx >> 8) & 3;
        int node  = idx >> 10;
        int h  = ntile * 8 + (lane >> 2);
        int k0 = ktile * 16 + (lane & 3) * 2;

        const float* wrow = W1 + ((size_t)node * H_SZ + h) * N_VARS;
        float2 wlo = *(const float2*)(wrow + k0);
        float2 whi = *(const float2*)(wrow + k0 + 8);
        const float* arow = adj + node * N_VARS;
        float2 alo = *(const float2*)(arow + k0);
        float2 ahi = *(const float2*)(arow + k0 + 8);
        if (node == N_VARS - 1) {   // hidden_flag: last node keeps only feature 63
            alo.x = 0.f; alo.y = 0.f;
            ahi.x = 0.f;
            if (k0 + 9 != N_VARS - 1) ahi.y = 0.f;
        }
        uint2 r;
        r.x = h2_as_u32(__floats2half2_rn(wlo.x * alo.x, wlo.y * alo.y));
        r.y = h2_as_u32(__floats2half2_rn(whi.x * ahi.x, whi.y * ahi.y));
        g_wfrag[idx] = r;
    }
}

// ---------------- main kernel: persistent CTAs, double-buffered X ----------------
__global__ void __launch_bounds__(256, 2)
main_kernel(const float* __restrict__ W2, float* __restrict__ out) {
    extern __shared__ char smem[];
    const int tid = threadIdx.x;
    const int lane = tid & 31, warp = tid >> 5;   // warp = node-in-group
    const int slice = blockIdx.x;                 // 0..36
    const int group = blockIdx.y;                 // 0..7

    float* w2s = (float*)(smem + SM_W2);
    float* outs = (float*)(smem + SM_OUT);
    const uint32_t sb = smem_u32(smem);

    // --- B fragments for this warp's node: 64 regs (ONCE per CTA) ---
    uint2 bf[4][8];
    {
        const uint2* src = g_wfrag + (size_t)(group * G_NODES + warp) * 1024 + lane;
#pragma unroll
        for (int kt = 0; kt < 4; kt++)
#pragma unroll
            for (int nt = 0; nt < 8; nt++)
                bf[kt][nt] = src[(kt * 8 + nt) * 32];
    }
    // --- W2 for this group ---
    if (tid < 128)
        ((float4*)w2s)[tid] = ((const float4*)(W2 + group * G_NODES * H_SZ))[tid];
    __syncthreads();

    const int mtx = lane >> 3, rowm = lane & 7;
    const int lq = lane & 3;       // quad col id
    const int lr = lane >> 2;      // row-in-8
    const uint32_t arow_off = (uint32_t)(((mtx & 1) * 8 + rowm) * XROW_B
                                         + ((mtx >> 1) * 8) * 2);
    float2 w2r[8];
#pragma unroll
    for (int nt = 0; nt < 8; nt++)
        w2r[nt] = *(const float2*)&w2s[warp * H_SZ + nt * 8 + lq * 2];

    // prefetch helper indexing: per-thread 4 chunks of 16B
    const int pr = tid >> 3, pseg = tid & 7;    // rows tid/8 + 32*it

    // --- prefetch first tile into buf0 ---
    {
        const char* src = (const char*)(g_x16 + (size_t)slice * TILE_M * N_VARS);
#pragma unroll
        for (int it = 0; it < 4; it++) {
            int r = pr + it * 32;
            cp_async16(sb + SM_X0 + (uint32_t)(r * XROW_B + pseg * 16),
                       src + r * 128 + pseg * 16);
        }
    }
    CP_COMMIT();

    int parity = 0;
#pragma unroll 1
    for (int bt = slice; bt < BTILES; bt += NSLICES) {
        // prefetch next tile into the other buffer (safe: all warps passed the
        // trailing __syncthreads of the previous iteration, so reads are done)
        {
            int nxt = bt + NSLICES;
            if (nxt < BTILES) {
                const char* src = (const char*)(g_x16 + (size_t)nxt * TILE_M * N_VARS);
                uint32_t dstb = sb + (parity ? SM_X0 : SM_X1);
#pragma unroll
                for (int it = 0; it < 4; it++) {
                    int r = pr + it * 32;
                    cp_async16(dstb + (uint32_t)(r * XROW_B + pseg * 16),
                               src + r * 128 + pseg * 16);
                }
            }
        }
        CP_COMMIT();
        CP_WAIT1();            // current tile's loads complete
        __syncthreads();       // visible to all warps; outs free for rewrite

        const uint32_t xsb = sb + (parity ? SM_X1 : SM_X0);
#pragma unroll 1
        for (int mt = 0; mt < MTILES; mt++) {
            const uint32_t mbase = xsb + (uint32_t)(mt * 16 * XROW_B) + arow_off;
            uint32_t a[4][4];
#pragma unroll
            for (int kt = 0; kt < 4; kt++)
                ldmatrix_x4(a[kt], mbase + (uint32_t)(kt * 32));

            float s0 = 0.f, s1 = 0.f;
#pragma unroll
            for (int nt = 0; nt < 8; nt++) {
                float c[4] = {0.f, 0.f, 0.f, 0.f};
#pragma unroll
                for (int kt = 0; kt < 4; kt++)
                    mma16816(c, a[kt], bf[kt][nt].x, bf[kt][nt].y);
                s0 = fmaf(fmaxf(c[0], 0.f), w2r[nt].x, s0);
                s0 = fmaf(fmaxf(c[1], 0.f), w2r[nt].y, s0);
                s1 = fmaf(fmaxf(c[2], 0.f), w2r[nt].x, s1);
                s1 = fmaf(fmaxf(c[3], 0.f), w2r[nt].y, s1);
            }
            s0 += __shfl_xor_sync(0xFFFFFFFF, s0, 1);
            s0 += __shfl_xor_sync(0xFFFFFFFF, s0, 2);
            s1 += __shfl_xor_sync(0xFFFFFFFF, s1, 1);
            s1 += __shfl_xor_sync(0xFFFFFFFF, s1, 2);
            if (lq == 0) {
                outs[(mt * 16 + lr) * G_NODES + warp] = s0;
                outs[(mt * 16 + lr + 8) * G_NODES + warp] = s1;
            }
        }
        __syncthreads();       // outs complete; X buffer free for future prefetch

        // coalesced store: 128 rows x 8 floats = 256 float4
        {
            int r = tid >> 1, q = tid & 1;
            float4 v = ((const float4*)outs)[tid];
            *(float4*)(out + (size_t)(bt * TILE_M + r) * N_VARS
                       + group * G_NODES + q * 4) = v;
        }
        parity ^= 1;
    }
}

// ---------------- launch ----------------
extern "C" void kernel_launch(void* const* d_in, const int* in_sizes, int n_in,
                              void* d_out, int out_size) {
    // metadata order: t, inputs, W1, W2, adjacency, discrete_mask
    const float* inputs = (const float*)d_in[1];
    const float* W1     = (const float*)d_in[2];
    const float* W2     = (const float*)d_in[3];
    const float* adj    = (const float*)d_in[4];
    float* out = (float*)d_out;

    static bool attr_set = false;
    if (!attr_set) {
        cudaFuncSetAttribute(main_kernel, cudaFuncAttributeMaxDynamicSharedMemorySize,
                             SM_TOTAL);
        attr_set = true;
    }

    prep_kernel<<<CVT_BLOCKS + FRAG_BLOCKS, 256>>>((const float4*)inputs, W1, adj);
    main_kernel<<<dim3(NSLICES, NODE_GROUPS), 256, SM_TOTAL>>>(W2, out);
}